// round 5
// baseline (speedup 1.0000x reference)
#include <cuda_runtime.h>
#include <cuda_bf16.h>
#include <cstdint>
#include <cstddef>

#define SEQ 65536
#define HID 128
#define NG  512
#define INP 64

// Permuted x-gate scratch (+2 steps of padding for unguarded prefetch)
static __device__ float g_xg[(size_t)(SEQ + 2) * NG];

union F2U { float2 f; unsigned long long u; };
union F4U { float4 v; struct { unsigned long long a, b; } u; };

static __device__ __forceinline__ unsigned long long ld2(const float2* p) {
    F2U u; u.f = *p; return u.u;
}
static __device__ __forceinline__ unsigned long long ffma2(unsigned long long a,
                                                           unsigned long long b,
                                                           unsigned long long c) {
    unsigned long long d;
    asm("fma.rn.f32x2 %0, %1, %2, %3;" : "=l"(d) : "l"(a), "l"(b), "l"(c));
    return d;
}
static __device__ __forceinline__ unsigned long long fadd2(unsigned long long a,
                                                           unsigned long long b) {
    unsigned long long d;
    asm("add.rn.f32x2 %0, %1, %2;" : "=l"(d) : "l"(a), "l"(b));
    return d;
}
static __device__ __forceinline__ float hsum2(unsigned long long a) {
    F2U u; u.u = a; return u.f.x + u.f.y;
}
static __device__ __forceinline__ uint32_t smem_u32(const void* p) {
    uint32_t a;
    asm("{ .reg .u64 t; cvta.to.shared.u64 t, %1; cvt.u32.u64 %0, t; }"
        : "=r"(a) : "l"(p));
    return a;
}
static __device__ __forceinline__ float ftanh(float x) {
    float y; asm("tanh.approx.f32 %0, %1;" : "=f"(y) : "f"(x)); return y;
}
static __device__ __forceinline__ void mbar_wait(uint32_t mb, uint32_t par) {
    asm volatile(
        "{\n\t.reg .pred P;\n"
        "W_%=:\n\t"
        "mbarrier.try_wait.parity.acquire.cta.shared::cta.b64 P, [%0], %1;\n\t"
        "@!P bra W_%=;\n\t}"
        :: "r"(mb), "r"(par) : "memory");
}
static __device__ __forceinline__ void mbar_rearm(uint32_t mb, uint32_t bytes) {
    asm volatile("mbarrier.arrive.expect_tx.shared.b64 _, [%0], %1;"
                 :: "r"(mb), "r"(bytes) : "memory");
}

// ---------------------------------------------------------------------------
// Phase 1: x_gates with permuted store layout (unchanged from R4):
//   row r = gate*128 + rank*64 + w*8 + jsub -> slot rank*256 + w*32 + gate*8 + jsub
// ---------------------------------------------------------------------------
__global__ void __launch_bounds__(512, 1)
gemm_xg(const float* __restrict__ x, const float* __restrict__ Wih,
        const float* __restrict__ bih, const float* __restrict__ bhh)
{
    __shared__ __align__(16) float xs[128 * INP];
    const int r  = threadIdx.x;
    const int t0 = blockIdx.x * 128;

    {
        const float4* src = (const float4*)(x + (size_t)t0 * INP);
        float4* dst = (float4*)xs;
        #pragma unroll
        for (int i = r; i < 128 * INP / 4; i += 512) dst[i] = src[i];
    }

    unsigned long long w[32];
    {
        const float2* wr = (const float2*)(Wih + (size_t)r * INP);
        #pragma unroll
        for (int i = 0; i < 32; i++) w[i] = ld2(wr + i);
    }
    const float bias = bih[r] + bhh[r];

    const int gate = r >> 7, rk = (r >> 6) & 1, w8 = (r >> 3) & 7, js = r & 7;
    const int slot = rk * 256 + w8 * 32 + gate * 8 + js;
    __syncthreads();

    for (int tt = 0; tt < 128; tt++) {
        const float2* xp = (const float2*)(xs + tt * INP);
        unsigned long long a0 = 0ull, a1 = 0ull, a2 = 0ull, a3 = 0ull;
        #pragma unroll
        for (int i = 0; i < 32; i += 4) {
            a0 = ffma2(w[i + 0], ld2(xp + i + 0), a0);
            a1 = ffma2(w[i + 1], ld2(xp + i + 1), a1);
            a2 = ffma2(w[i + 2], ld2(xp + i + 2), a2);
            a3 = ffma2(w[i + 3], ld2(xp + i + 3), a3);
        }
        g_xg[(size_t)(t0 + tt) * NG + slot] =
            hsum2(fadd2(fadd2(a0, a1), fadd2(a2, a3))) + bias;
    }
}

// ---------------------------------------------------------------------------
// Phase 2+3: K-SPLIT 2-CTA cluster scan.
// CTA `rank` holds W_hh[:, rank*64 : rank*64+64] for ALL 512 rows.
// Per step: partials for the peer's 256 rows (from local h half) -> st.async
// early; own 256 rows' partials under the transit; wait; combine+activate+
// update own h half. Double-buffered pbuf/h_s/barriers by step parity.
// ---------------------------------------------------------------------------
__global__ void __launch_bounds__(256, 1) __cluster_dims__(2, 1, 1)
lstm_scan(const float* __restrict__ Whh,
          const float* __restrict__ Wlin,
          const float* __restrict__ blin,
          float* __restrict__ out)
{
    __shared__ __align__(16) float h_s[2][64];
    __shared__ __align__(16) float pbuf[2][256];
    __shared__ __align__(8)  unsigned long long mbar[2];
    __shared__ __align__(8)  unsigned long long mbar_fin;

    const int tid  = threadIdx.x;
    const int w_id = tid >> 5;
    const int lane = tid & 31;
    const int gate = lane >> 3;
    const int jsub = lane & 7;

    uint32_t rank;
    asm("mov.u32 %0, %%cluster_ctarank;" : "=r"(rank));
    const uint32_t peer = rank ^ 1u;

    // row indices (gate-major as before); k-half = rank*64
    const int r_own  = gate * HID + (int)rank * 64 + w_id * 8 + jsub;
    const int r_peer = gate * HID + (int)peer * 64 + w_id * 8 + jsub;
    const int kof    = (int)rank * 32;            // float2 offset of my k-half

    unsigned long long wo[32], wp[32];
    {
        const float2* a = (const float2*)(Whh + (size_t)r_own  * HID) + kof;
        const float2* b = (const float2*)(Whh + (size_t)r_peer * HID) + kof;
        #pragma unroll
        for (int i = 0; i < 32; i++) wo[i] = ld2(a + i);
        #pragma unroll
        for (int i = 0; i < 32; i++) wp[i] = ld2(b + i);
    }

    if (tid < 64)  { h_s[0][tid] = 0.0f; h_s[1][tid] = 0.0f; }
    const uint32_t mb0 = smem_u32(&mbar[0]);
    const uint32_t mb1 = smem_u32(&mbar[1]);
    const uint32_t mbf = smem_u32(&mbar_fin);
    if (tid == 0) {
        asm volatile("mbarrier.init.shared.b64 [%0], 1;" :: "r"(mb0) : "memory");
        asm volatile("mbarrier.init.shared.b64 [%0], 1;" :: "r"(mb1) : "memory");
        asm volatile("mbarrier.init.shared.b64 [%0], 1;" :: "r"(mbf) : "memory");
        mbar_rearm(mb0, 1024);
        mbar_rearm(mb1, 1024);
        mbar_rearm(mbf, 4);
    }
    // peer addresses: barriers + this thread's partial slot in each pbuf
    uint32_t pmb[2], pdst[2];
    asm("mapa.shared::cluster.u32 %0, %1, %2;" : "=r"(pmb[0]) : "r"(mb0), "r"(peer));
    asm("mapa.shared::cluster.u32 %0, %1, %2;" : "=r"(pmb[1]) : "r"(mb1), "r"(peer));
    const uint32_t pb_a = smem_u32(&pbuf[0][0]);
    asm("mapa.shared::cluster.u32 %0, %1, %2;"
        : "=r"(pdst[0]) : "r"(pb_a + (uint32_t)tid * 4u), "r"(peer));
    asm("mapa.shared::cluster.u32 %0, %1, %2;"
        : "=r"(pdst[1]) : "r"(pb_a + 1024u + (uint32_t)tid * 4u), "r"(peer));
    uint32_t pfin_dst, pmbf;
    asm("mapa.shared::cluster.u32 %0, %1, %2;" : "=r"(pfin_dst) : "r"(pb_a), "r"(peer));
    asm("mapa.shared::cluster.u32 %0, %1, %2;" : "=r"(pmbf) : "r"(mbf), "r"(peer));

    __syncthreads();
    asm volatile("barrier.cluster.arrive.aligned;" ::: "memory");
    asm volatile("barrier.cluster.wait.aligned;"   ::: "memory");

    // branchless activation: y = aa*tanh(kk*s) + bb   (sigmoid = 0.5+0.5*tanh(x/2))
    const float kk = (gate == 2) ? 1.0f : 0.5f;
    const float aa = (gate == 2) ? 1.0f : 0.5f;
    const float bb = (gate == 2) ? 0.0f : 0.5f;

    float c = 0.0f;
    uint32_t par0 = 0, par1 = 0;
    const float* xq = g_xg + (size_t)rank * 256 + (size_t)w_id * 32 + lane;
    float xcur[2];
    xcur[0] = xq[0];
    xcur[1] = xq[NG];

    const int jl = w_id * 8 + lane;   // local h index (valid lane<8)

#define KSTEP(B)                                                               \
    {                                                                          \
        const float4* hp = (const float4*)h_s[(B) ^ 1];                        \
        /* peer-row partial first: send ASAP */                                \
        unsigned long long p0 = 0ull, p1 = 0ull, p2 = 0ull, p3 = 0ull;         \
        _Pragma("unroll")                                                      \
        for (int i = 0; i < 16; i += 4) {                                      \
            F4U q0, q1, q2, q3;                                                \
            q0.v = hp[i + 0]; q1.v = hp[i + 1];                                \
            q2.v = hp[i + 2]; q3.v = hp[i + 3];                                \
            p0 = ffma2(wp[2 * i + 0], q0.u.a, p0);                             \
            p1 = ffma2(wp[2 * i + 1], q0.u.b, p1);                             \
            p2 = ffma2(wp[2 * i + 2], q1.u.a, p2);                             \
            p3 = ffma2(wp[2 * i + 3], q1.u.b, p3);                             \
            p0 = ffma2(wp[2 * i + 4], q2.u.a, p0);                             \
            p1 = ffma2(wp[2 * i + 5], q2.u.b, p1);                             \
            p2 = ffma2(wp[2 * i + 6], q3.u.a, p2);                             \
            p3 = ffma2(wp[2 * i + 7], q3.u.b, p3);                             \
        }                                                                      \
        const float sp = hsum2(fadd2(fadd2(p0, p1), fadd2(p2, p3)));           \
        asm volatile(                                                          \
            "st.async.shared::cluster.mbarrier::complete_tx::bytes.b32 "       \
            "[%0], %1, [%2];"                                                  \
            :: "r"(pdst[B]), "r"(__float_as_uint(sp)), "r"(pmb[B])             \
            : "memory");                                                       \
        /* own-row partial under the transit */                                \
        F2U ii; ii.f.x = xcur[B]; ii.f.y = 0.0f;                               \
        xcur[B] = xq[2 * NG];                                                  \
        xq += NG;                                                              \
        unsigned long long a0 = ii.u, a1 = 0ull, a2 = 0ull, a3 = 0ull;         \
        _Pragma("unroll")                                                      \
        for (int i = 0; i < 16; i += 4) {                                      \
            F4U q0, q1, q2, q3;                                                \
            q0.v = hp[i + 0]; q1.v = hp[i + 1];                                \
            q2.v = hp[i + 2]; q3.v = hp[i + 3];                                \
            a0 = ffma2(wo[2 * i + 0], q0.u.a, a0);                             \
            a1 = ffma2(wo[2 * i + 1], q0.u.b, a1);                             \
            a2 = ffma2(wo[2 * i + 2], q1.u.a, a2);                             \
            a3 = ffma2(wo[2 * i + 3], q1.u.b, a3);                             \
            a0 = ffma2(wo[2 * i + 4], q2.u.a, a0);                             \
            a1 = ffma2(wo[2 * i + 5], q2.u.b, a1);                             \
            a2 = ffma2(wo[2 * i + 6], q3.u.a, a2);                             \
            a3 = ffma2(wo[2 * i + 7], q3.u.b, a3);                             \
        }                                                                      \
        const float so = hsum2(fadd2(fadd2(a0, a1), fadd2(a2, a3)));           \
        /* wait for peer partials */                                           \
        const uint32_t mbc = (B) ? mb1 : mb0;                                  \
        mbar_wait(mbc, (B) ? par1 : par0);                                     \
        if (B) par1 ^= 1u; else par0 ^= 1u;                                    \
        if (tid == 0) mbar_rearm(mbc, 1024);                                   \
        /* combine + activate + update */                                      \
        const float y = fmaf(aa, ftanh(kk * (so + pbuf[B][tid])), bb);         \
        const float iv = __shfl_sync(0xffffffffu, y, jsub);                    \
        const float fv = __shfl_sync(0xffffffffu, y, jsub + 8);                \
        const float gv = __shfl_sync(0xffffffffu, y, jsub + 16);               \
        const float ov = __shfl_sync(0xffffffffu, y, jsub + 24);               \
        c = fmaf(fv, c, iv * gv);                                              \
        const float hv = ov * ftanh(c);                                        \
        if (lane < 8) h_s[B][jl] = hv;                                         \
        __syncthreads();                                                       \
    }

    for (int t = 0; t < SEQ; t += 2) {
        KSTEP(0)
        KSTEP(1)
    }

    // h(T) lives in h_s[1] (last step parity 1); each CTA has its own half.
    if (rank == 1) {
        if (w_id == 0) {
            float s = h_s[1][lane] * Wlin[64 + lane]
                    + h_s[1][32 + lane] * Wlin[96 + lane];
            #pragma unroll
            for (int d = 16; d > 0; d >>= 1)
                s += __shfl_xor_sync(0xffffffffu, s, d);
            if (lane == 0) {
                asm volatile(
                    "st.async.shared::cluster.mbarrier::complete_tx::bytes.b32 "
                    "[%0], %1, [%2];"
                    :: "r"(pfin_dst), "r"(__float_as_uint(s)), "r"(pmbf)
                    : "memory");
            }
        }
    } else {
        if (w_id == 0) {
            mbar_wait(mbf, 0);
            float s = h_s[1][lane] * Wlin[lane]
                    + h_s[1][32 + lane] * Wlin[32 + lane];
            #pragma unroll
            for (int d = 16; d > 0; d >>= 1)
                s += __shfl_xor_sync(0xffffffffu, s, d);
            if (lane == 0) {
                const float acc = s + pbuf[0][0] + blin[0];
                out[0] = fmaf(0.5f, ftanh(0.5f * acc), 0.5f);
            }
        }
    }

    asm volatile("barrier.cluster.arrive.aligned;" ::: "memory");
    asm volatile("barrier.cluster.wait.aligned;"   ::: "memory");
}

extern "C" void kernel_launch(void* const* d_in, const int* in_sizes, int n_in,
                              void* d_out, int out_size) {
    const float* input = (const float*)d_in[0];
    const float* Wih   = (const float*)d_in[1];
    const float* Whh   = (const float*)d_in[2];
    const float* bih   = (const float*)d_in[3];
    const float* bhh   = (const float*)d_in[4];
    const float* Wlin  = (const float*)d_in[5];
    const float* blin  = (const float*)d_in[6];
    float* out = (float*)d_out;

    gemm_xg<<<SEQ / 128, 512>>>(input, Wih, bih, bhh);
    lstm_scan<<<2, 256>>>(Whh, Wlin, blin, out);
}

// round 6
// speedup vs baseline: 1.1711x; 1.1711x over previous
#include <cuda_runtime.h>
#include <cuda_fp16.h>
#include <cstdint>
#include <cstddef>

#define SEQ 65536
#define HID 128
#define NG  512
#define INP 64

// Permuted x-gate scratch (+2 steps padding for unguarded prefetch)
static __device__ float g_xg[(size_t)(SEQ + 2) * NG];

union F2U { float2 f; unsigned long long u; };
union H4U { float4 v; __half2 h[4]; };

static __device__ __forceinline__ unsigned long long ld2(const float2* p) {
    F2U u; u.f = *p; return u.u;
}
static __device__ __forceinline__ unsigned long long ffma2(unsigned long long a,
                                                           unsigned long long b,
                                                           unsigned long long c) {
    unsigned long long d;
    asm("fma.rn.f32x2 %0, %1, %2, %3;" : "=l"(d) : "l"(a), "l"(b), "l"(c));
    return d;
}
static __device__ __forceinline__ unsigned long long fadd2(unsigned long long a,
                                                           unsigned long long b) {
    unsigned long long d;
    asm("add.rn.f32x2 %0, %1, %2;" : "=l"(d) : "l"(a), "l"(b));
    return d;
}
static __device__ __forceinline__ float hsum2(unsigned long long a) {
    F2U u; u.u = a; return u.f.x + u.f.y;
}
static __device__ __forceinline__ float ftanh(float x) {
    float y; asm("tanh.approx.f32 %0, %1;" : "=f"(y) : "f"(x)); return y;
}

// ---------------------------------------------------------------------------
// Phase 1: x_gates, permuted so each scan warp reads 32 consecutive floats:
//   row r = gate*128 + j  (gate=r>>7, j=r&127, w8=j>>3, js=j&7)
//   slot  = w8*32 + gate*8 + js
// ---------------------------------------------------------------------------
__global__ void __launch_bounds__(512, 1)
gemm_xg(const float* __restrict__ x, const float* __restrict__ Wih,
        const float* __restrict__ bih, const float* __restrict__ bhh)
{
    __shared__ __align__(16) float xs[128 * INP];
    const int r  = threadIdx.x;
    const int t0 = blockIdx.x * 128;

    {
        const float4* src = (const float4*)(x + (size_t)t0 * INP);
        float4* dst = (float4*)xs;
        #pragma unroll
        for (int i = r; i < 128 * INP / 4; i += 512) dst[i] = src[i];
    }

    unsigned long long w[32];
    {
        const float2* wr = (const float2*)(Wih + (size_t)r * INP);
        #pragma unroll
        for (int i = 0; i < 32; i++) w[i] = ld2(wr + i);
    }
    const float bias = bih[r] + bhh[r];

    const int gate = r >> 7, j = r & 127, w8 = j >> 3, js = j & 7;
    const int slot = w8 * 32 + gate * 8 + js;
    __syncthreads();

    for (int tt = 0; tt < 128; tt++) {
        const float2* xp = (const float2*)(xs + tt * INP);
        unsigned long long a0 = 0ull, a1 = 0ull, a2 = 0ull, a3 = 0ull;
        #pragma unroll
        for (int i = 0; i < 32; i += 4) {
            a0 = ffma2(w[i + 0], ld2(xp + i + 0), a0);
            a1 = ffma2(w[i + 1], ld2(xp + i + 1), a1);
            a2 = ffma2(w[i + 2], ld2(xp + i + 2), a2);
            a3 = ffma2(w[i + 3], ld2(xp + i + 3), a3);
        }
        g_xg[(size_t)(t0 + tt) * NG + slot] =
            hsum2(fadd2(fadd2(a0, a1), fadd2(a2, a3))) + bias;
    }
}

// ---------------------------------------------------------------------------
// Phase 2+3: SINGLE-CTA scan, W_hh fully register-resident as f16x2.
// 512 threads = 512 gate rows. Warp w, lane l: gate=l>>3, jsub=l&7,
// j = w*8+jsub, row = gate*128+j. h in SMEM as f16, double-buffered.
// One bar.sync per step; zero cluster traffic.
// ---------------------------------------------------------------------------
__global__ void __launch_bounds__(512, 1)
lstm_scan(const float* __restrict__ Whh,
          const float* __restrict__ Wlin,
          const float* __restrict__ blin,
          float* __restrict__ out)
{
    __shared__ __align__(16) __half h_s[2][HID];

    const int tid  = threadIdx.x;
    const int w_id = tid >> 5;
    const int lane = tid & 31;
    const int gate = lane >> 3;
    const int jsub = lane & 7;
    const int j    = w_id * 8 + jsub;
    const int row  = gate * HID + j;

    // Convert this row of W_hh to f16x2 registers (one-time)
    __half2 w[64];
    {
        const float2* wr = (const float2*)(Whh + (size_t)row * HID);
        #pragma unroll
        for (int i = 0; i < 64; i++) w[i] = __float22half2_rn(wr[i]);
    }

    if (tid < 2 * HID) ((__half*)h_s)[tid] = __float2half_rn(0.0f);

    // activation: y = aa*tanh(kk*s)+bb  (sigmoid(x) = 0.5 + 0.5*tanh(x/2))
    const float kk = (gate == 2) ? 1.0f : 0.5f;
    const float aa = (gate == 2) ? 1.0f : 0.5f;
    const float bb = (gate == 2) ? 0.0f : 0.5f;

    float c = 0.0f;
    const float* xq = g_xg + w_id * 32 + lane;
    float xcur[2];
    xcur[0] = xq[0];
    xcur[1] = xq[NG];

    __syncthreads();

#define STEP(B)                                                                \
    {                                                                          \
        const float4* hp = (const float4*)h_s[(B) ^ 1];                        \
        __half2 a0 = __float2half2_rn(0.0f), a1 = a0, a2 = a0, a3 = a0;        \
        _Pragma("unroll")                                                      \
        for (int i = 0; i < 16; i++) {                                         \
            H4U q; q.v = hp[i];                                                \
            a0 = __hfma2(w[4 * i + 0], q.h[0], a0);                            \
            a1 = __hfma2(w[4 * i + 1], q.h[1], a1);                            \
            a2 = __hfma2(w[4 * i + 2], q.h[2], a2);                            \
            a3 = __hfma2(w[4 * i + 3], q.h[3], a3);                            \
        }                                                                      \
        a0 = __hadd2(a0, a1);                                                  \
        a2 = __hadd2(a2, a3);                                                  \
        a0 = __hadd2(a0, a2);                                                  \
        const float s = xcur[B] + __low2float(a0) + __high2float(a0);          \
        xcur[B] = xq[2 * NG];                                                  \
        xq += NG;                                                              \
        const float y = fmaf(aa, ftanh(kk * s), bb);                           \
        const float iv = __shfl_sync(0xffffffffu, y, jsub);                    \
        const float fv = __shfl_sync(0xffffffffu, y, jsub + 8);                \
        const float gv = __shfl_sync(0xffffffffu, y, jsub + 16);               \
        const float ov = __shfl_sync(0xffffffffu, y, jsub + 24);               \
        c = fmaf(fv, c, iv * gv);                                              \
        const float hv = ov * ftanh(c);                                        \
        if (lane < 8) h_s[B][w_id * 8 + lane] = __float2half_rn(hv);           \
        __syncthreads();                                                       \
    }

    for (int t = 0; t < SEQ; t += 2) {
        STEP(0)
        STEP(1)
    }

    // h_T is in h_s[1] (last step B=1). Warp 0 reduces the linear layer.
    if (tid < 32) {
        float s = 0.0f;
        #pragma unroll
        for (int m = 0; m < 4; m++)
            s += __half2float(h_s[1][lane + 32 * m]) * Wlin[lane + 32 * m];
        #pragma unroll
        for (int d = 16; d > 0; d >>= 1)
            s += __shfl_xor_sync(0xffffffffu, s, d);
        if (lane == 0)
            out[0] = fmaf(0.5f, ftanh(0.5f * (s + blin[0])), 0.5f);
    }
}

extern "C" void kernel_launch(void* const* d_in, const int* in_sizes, int n_in,
                              void* d_out, int out_size) {
    const float* input = (const float*)d_in[0];
    const float* Wih   = (const float*)d_in[1];
    const float* Whh   = (const float*)d_in[2];
    const float* bih   = (const float*)d_in[3];
    const float* bhh   = (const float*)d_in[4];
    const float* Wlin  = (const float*)d_in[5];
    const float* blin  = (const float*)d_in[6];
    float* out = (float*)d_out;

    gemm_xg<<<SEQ / 128, 512>>>(input, Wih, bih, bhh);
    lstm_scan<<<1, 512>>>(Whh, Wlin, blin, out);
}